// round 10
// baseline (speedup 1.0000x reference)
#include <cuda_runtime.h>
#include <cstdint>

// x [4,512,128] f32, y [512,128] f32 -> out [4,512,512,3] f32 (cos, L1, L2)
#define R_TOTAL 2048
#define C_TOTAL 512
#define D_DIM   128
#define NDD2    64              // packed-pair (2 D-values) steps
#define NC      32              // c-pairs (2 dd2 each)

#define BM 64
#define BN 64
#define XR  65                  // x stride per c, in ull2 (64 rows + 1 pad)
#define YTS 66                  // y stride per dd2, in u64 (64 rows + 2 pad)
#define X_WORDS (NC * XR * 2)                      // u64 words = 4160
#define NORM_OFF (X_WORDS + NDD2 * YTS)            // u64 offset of norm area
#define SMEM_BYTES (NORM_OFF * 8 + 128 * 2 * 4)

typedef unsigned long long u64;
struct __align__(16) ull2 { u64 x, y; };

// ---------------- packed f32x2 helpers ----------------
__device__ __forceinline__ u64 ffma2(u64 a, u64 b, u64 c) {
    u64 d;
    asm("fma.rn.f32x2 %0, %1, %2, %3;" : "=l"(d) : "l"(a), "l"(b), "l"(c));
    return d;
}
__device__ __forceinline__ u64 fadd2(u64 a, u64 b) {
    u64 d;
    asm("add.rn.f32x2 %0, %1, %2;" : "=l"(d) : "l"(a), "l"(b));
    return d;
}
__device__ __forceinline__ float f2lo(u64 d) { return __uint_as_float((unsigned)(d & 0xFFFFFFFFu)); }
__device__ __forceinline__ float f2hi(u64 d) { return __uint_as_float((unsigned)(d >> 32)); }
__device__ __forceinline__ u64 pack2(float lo, float hi) {
    return ((u64)__float_as_uint(hi) << 32) | (u64)__float_as_uint(lo);
}

// 16 packed-pair updates for one dd2
__device__ __forceinline__ void comp16(u64 x0, u64 x1, u64 x2, u64 x3,
                                       u64 y0, u64 y1, u64 y2, u64 y3,
                                       u64 (&a1)[4][4], u64 (&a2)[4][4]) {
    const u64 ABSM = 0x7FFFFFFF7FFFFFFFULL;
    u64 xv[4] = { x0, x1, x2, x3 };
    u64 yv[4] = { y0, y1, y2, y3 };
    #pragma unroll
    for (int i = 0; i < 4; i++) {
        #pragma unroll
        for (int j = 0; j < 4; j++) {
            u64 d = fadd2(xv[i], yv[j]);          // x + (-y), FADD2 rt=2
            a2[i][j] = ffma2(d, d, a2[i][j]);
            a1[i][j] = fadd2(a1[i][j], d & ABSM);
        }
    }
}

// ---------------- fused distance kernel ----------------
// 256 threads: tx = t&15 -> y rows {4tx..4tx+3}; ty = t>>4 -> x rows ty+16i
// x smem: ull2[c][row]  (each ull2 = dd2 2c and 2c+1 for that row)
// y smem: u64 [dd2][row], NEGATED.
__global__ void __launch_bounds__(256, 2)
dist_kernel(const float* __restrict__ x, const float* __restrict__ y,
            float* __restrict__ out) {
    extern __shared__ __align__(16) u64 sm64[];
    ull2* xs2 = reinterpret_cast<ull2*>(sm64);     // [NC][XR]
    u64*  ysT = sm64 + X_WORDS;                    // [NDD2][YTS] (holds -y)
    float* nsq = reinterpret_cast<float*>(sm64 + NORM_OFF);  // [128]: 64 x + 64 y
    float* nrn = nsq + 128;

    const int R0 = blockIdx.x * BM;     // grid.x = 32
    const int C0 = blockIdx.y * BN;     // grid.y = 8
    const int t  = threadIdx.x;
    const int tx = t & 15;
    const int ty = t >> 4;

    // ---- stage x tile: ull2 per (c, row)
    #pragma unroll
    for (int s = 0; s < 8; s++) {
        int idx = t + 256 * s;          // 0..2047
        int row = idx >> 5;             // 0..63
        int c   = idx & 31;             // dd2 pair index
        float4 v = *reinterpret_cast<const float4*>(
            x + (size_t)(R0 + row) * D_DIM + c * 4);
        ull2 w; w.x = pack2(v.x, v.y); w.y = pack2(v.z, v.w);
        xs2[c * XR + row] = w;
    }
    // ---- stage y tile NEGATED: u64 per (dd2, row)
    #pragma unroll
    for (int s = 0; s < 8; s++) {
        int idx  = t + 256 * s;
        int row  = idx >> 5;
        int col4 = idx & 31;
        float4 v = *reinterpret_cast<const float4*>(
            y + (size_t)(C0 + row) * D_DIM + col4 * 4);
        ysT[(2 * col4) * YTS + row]     = pack2(-v.x, -v.y);
        ysT[(2 * col4 + 1) * YTS + row] = pack2(-v.z, -v.w);
    }
    __syncthreads();

    // ---- fused norms ((-y)^2 == y^2)
    if (t < 128) {
        u64 a = 0ULL;
        if (t < 64) {
            #pragma unroll 8
            for (int c = 0; c < NC; c++) {
                ull2 v = xs2[c * XR + t];
                a = ffma2(v.x, v.x, a);
                a = ffma2(v.y, v.y, a);
            }
        } else {
            const u64* base = ysT + (t - 64);
            #pragma unroll 8
            for (int dd2 = 0; dd2 < NDD2; dd2++) {
                u64 v = base[dd2 * YTS];
                a = ffma2(v, v, a);
            }
        }
        float s = f2lo(a) + f2hi(a);
        nsq[t] = s;
        nrn[t] = rsqrtf(s);
    }
    __syncthreads();

    u64 acc1[4][4];   // packed L1 sums   [x-row i][y-col j]
    u64 acc2[4][4];   // packed sum of squares
    #pragma unroll
    for (int i = 0; i < 4; i++)
        #pragma unroll
        for (int j = 0; j < 4; j++) { acc1[i][j] = 0ULL; acc2[i][j] = 0ULL; }

    const ull2* pxc = xs2 + ty;                    // + c*XR + 16*i
    const u64*  pyc = ysT + 4 * tx;                // + dd2*YTS

    // ---- software-pipelined mainloop: 4 dd2 (2 c-pairs) per iteration,
    //      two named buffer sets, every load writes its own registers.
    ull2 xA0 = pxc[0], xA1 = pxc[16], xA2 = pxc[32], xA3 = pxc[48];
    ull2 e0 = *reinterpret_cast<const ull2*>(pyc);
    ull2 e1 = *reinterpret_cast<const ull2*>(pyc + 2);
    ull2 xB0, xB1, xB2, xB3;

    for (int c = 0; c < NC; c += 2) {
        // dd2 = 2c  (x = xA.lo, y = e)
        ull2 o0 = *reinterpret_cast<const ull2*>(pyc + 1 * YTS);
        ull2 o1 = *reinterpret_cast<const ull2*>(pyc + 1 * YTS + 2);
        comp16(xA0.x, xA1.x, xA2.x, xA3.x, e0.x, e0.y, e1.x, e1.y, acc1, acc2);

        // prefetch pair c+1 x, and y for dd2 = 2c+2
        xB0 = pxc[XR];      xB1 = pxc[XR + 16];
        xB2 = pxc[XR + 32]; xB3 = pxc[XR + 48];
        ull2 f0 = *reinterpret_cast<const ull2*>(pyc + 2 * YTS);
        ull2 f1 = *reinterpret_cast<const ull2*>(pyc + 2 * YTS + 2);

        // dd2 = 2c+1  (x = xA.hi, y = o)
        comp16(xA0.y, xA1.y, xA2.y, xA3.y, o0.x, o0.y, o1.x, o1.y, acc1, acc2);

        // dd2 = 2c+2  (x = xB.lo, y = f)
        ull2 p0 = *reinterpret_cast<const ull2*>(pyc + 3 * YTS);
        ull2 p1 = *reinterpret_cast<const ull2*>(pyc + 3 * YTS + 2);
        comp16(xB0.x, xB1.x, xB2.x, xB3.x, f0.x, f0.y, f1.x, f1.y, acc1, acc2);

        // prefetch next iteration's xA / e
        if (c + 2 < NC) {
            xA0 = pxc[2 * XR];      xA1 = pxc[2 * XR + 16];
            xA2 = pxc[2 * XR + 32]; xA3 = pxc[2 * XR + 48];
            e0 = *reinterpret_cast<const ull2*>(pyc + 4 * YTS);
            e1 = *reinterpret_cast<const ull2*>(pyc + 4 * YTS + 2);
        }

        // dd2 = 2c+3  (x = xB.hi, y = p)
        comp16(xB0.y, xB1.y, xB2.y, xB3.y, p0.x, p0.y, p1.x, p1.y, acc1, acc2);

        pxc += 2 * XR;
        pyc += 4 * YTS;
    }

    // ---- epilogue: cos / p1 / p2, 3x STG.128 per x-row ----
    #pragma unroll
    for (int i = 0; i < 4; i++) {
        int lrow = ty + 16 * i;
        int gr = R0 + lrow;
        float xsq = nsq[lrow];
        float xrn = nrn[lrow];
        float o[12];
        #pragma unroll
        for (int j = 0; j < 4; j++) {
            int lcol = 4 * tx + j;
            float s2 = f2lo(acc2[i][j]) + f2hi(acc2[i][j]);
            float s1 = f2lo(acc1[i][j]) + f2hi(acc1[i][j]);
            float p2 = sqrtf(fmaxf(s2, 0.0f));
            float dot = 0.5f * (xsq + nsq[64 + lcol] - s2);
            float cosv = dot * xrn * nrn[64 + lcol];
            o[3 * j + 0] = cosv;
            o[3 * j + 1] = s1;
            o[3 * j + 2] = p2;
        }
        size_t base = ((size_t)gr * C_TOTAL + C0 + 4 * tx) * 3;
        float4* dst = reinterpret_cast<float4*>(out + base);
        dst[0] = make_float4(o[0], o[1], o[2],  o[3]);
        dst[1] = make_float4(o[4], o[5], o[6],  o[7]);
        dst[2] = make_float4(o[8], o[9], o[10], o[11]);
    }
}

extern "C" void kernel_launch(void* const* d_in, const int* in_sizes, int n_in,
                              void* d_out, int out_size) {
    const float* x = (const float*)d_in[0];
    const float* y = (const float*)d_in[1];
    float* out = (float*)d_out;

    cudaFuncSetAttribute(dist_kernel,
                         cudaFuncAttributeMaxDynamicSharedMemorySize, SMEM_BYTES);

    dim3 grid(R_TOTAL / BM, C_TOTAL / BN);   // 32 x 8 = 256 blocks, 2 CTA/SM
    dist_kernel<<<grid, 256, SMEM_BYTES>>>(x, y, out);
}

// round 11
// speedup vs baseline: 1.1728x; 1.1728x over previous
#include <cuda_runtime.h>
#include <cstdint>

// x [4,512,128] f32, y [512,128] f32 -> out [4,512,512,3] f32 (cos, L1, L2)
#define R_TOTAL 2048
#define C_TOTAL 512
#define D_DIM   128
#define DKC     64              // D per chunk
#define NDD2C   (DKC / 2)       // 32 packed-pair steps per chunk
#define NCHUNK  (D_DIM / DKC)   // 2

#define BM 64                   // x rows per block
#define BN 32                   // y rows per block
#define XTS 65                  // xsT row stride in u64 ([dd2][row=64]+1 pad)
#define YTS 34                  // ysT row stride in u64 ([dd2][row=32]+2 pad, 16B align)
#define SMEM_WORDS (NDD2C * XTS + NDD2C * YTS)   // 2080+1088=3168 u64 = 25344 B

typedef unsigned long long u64;
struct __align__(16) ull2 { u64 x, y; };

// ---------------- precomputed norms ----------------
__device__ float g_xsq[R_TOTAL];
__device__ float g_xrn[R_TOTAL];
__device__ float g_ysq[C_TOTAL];
__device__ float g_yrn[C_TOTAL];

__global__ void norms_kernel(const float* __restrict__ x,
                             const float* __restrict__ y) {
    int w    = (blockIdx.x * blockDim.x + threadIdx.x) >> 5;
    int lane = threadIdx.x & 31;
    if (w >= R_TOTAL + C_TOTAL) return;
    const float* p = (w < R_TOTAL) ? (x + (size_t)w * D_DIM)
                                   : (y + (size_t)(w - R_TOTAL) * D_DIM);
    float4 v = reinterpret_cast<const float4*>(p)[lane];
    float s = v.x * v.x + v.y * v.y + v.z * v.z + v.w * v.w;
    #pragma unroll
    for (int o = 16; o > 0; o >>= 1) s += __shfl_xor_sync(0xFFFFFFFFu, s, o);
    if (lane == 0) {
        float r = rsqrtf(s);
        if (w < R_TOTAL) { g_xsq[w] = s; g_xrn[w] = r; }
        else             { g_ysq[w - R_TOTAL] = s; g_yrn[w - R_TOTAL] = r; }
    }
}

// ---------------- packed f32x2 helpers ----------------
__device__ __forceinline__ u64 ffma2(u64 a, u64 b, u64 c) {
    u64 d;
    asm("fma.rn.f32x2 %0, %1, %2, %3;" : "=l"(d) : "l"(a), "l"(b), "l"(c));
    return d;
}
__device__ __forceinline__ u64 fadd2(u64 a, u64 b) {
    u64 d;
    asm("add.rn.f32x2 %0, %1, %2;" : "=l"(d) : "l"(a), "l"(b));
    return d;
}
__device__ __forceinline__ float f2lo(u64 d) { return __uint_as_float((unsigned)(d & 0xFFFFFFFFu)); }
__device__ __forceinline__ float f2hi(u64 d) { return __uint_as_float((unsigned)(d >> 32)); }
__device__ __forceinline__ u64 pack2(float lo, float hi) {
    return ((u64)__float_as_uint(hi) << 32) | (u64)__float_as_uint(lo);
}

// ---------------- main distance kernel ----------------
// 256 threads: tx = t&15 -> y cols {2tx, 2tx+1}; ty = t>>4 -> x rows ty+16i (i<4)
// y tile stored NEGATED: diff = x + (-y) is FADD2 (rt=2).
// 25.3 KB smem/CTA -> 4 CTAs/SM with 100% carveout; 64-reg budget via bounds.
__global__ void __launch_bounds__(256, 4)
dist_kernel(const float* __restrict__ x, const float* __restrict__ y,
            float* __restrict__ out) {
    __shared__ __align__(16) u64 sm64[SMEM_WORDS];
    u64* xsT = sm64;                    // [NDD2C][XTS]
    u64* ysT = sm64 + NDD2C * XTS;      // [NDD2C][YTS]  (holds -y)

    const int R0 = blockIdx.x * BM;     // grid.x = 32
    const int C0 = blockIdx.y * BN;     // grid.y = 16
    const int t  = threadIdx.x;
    const int tx = t & 15;
    const int ty = t >> 4;

    const u64 ABSM = 0x7FFFFFFF7FFFFFFFULL;   // packed abs mask

    u64 acc1[4][2];   // packed L1 sums   [x-row i][y-col j]
    u64 acc2[4][2];   // packed sum of squares
    #pragma unroll
    for (int i = 0; i < 4; i++)
        #pragma unroll
        for (int j = 0; j < 2; j++) { acc1[i][j] = 0ULL; acc2[i][j] = 0ULL; }

    #pragma unroll
    for (int ch = 0; ch < NCHUNK; ch++) {
        const int d0 = ch * DKC;

        // ---- stage x chunk (64 rows x 64 cols): 4 float4 per thread
        #pragma unroll
        for (int s = 0; s < 4; s++) {
            int idx  = t + 256 * s;     // 0..1023
            int row  = idx >> 4;        // 0..63
            int col4 = idx & 15;        // float4 slot within chunk
            float4 v = *reinterpret_cast<const float4*>(
                x + (size_t)(R0 + row) * D_DIM + d0 + col4 * 4);
            xsT[(2 * col4) * XTS + row]     = pack2(v.x, v.y);
            xsT[(2 * col4 + 1) * XTS + row] = pack2(v.z, v.w);
        }
        // ---- stage y chunk NEGATED (32 rows x 64 cols): 2 float4 per thread
        #pragma unroll
        for (int s = 0; s < 2; s++) {
            int idx  = t + 256 * s;     // 0..511
            int row  = idx >> 4;        // 0..31
            int col4 = idx & 15;
            float4 v = *reinterpret_cast<const float4*>(
                y + (size_t)(C0 + row) * D_DIM + d0 + col4 * 4);
            ysT[(2 * col4) * YTS + row]     = pack2(-v.x, -v.y);
            ysT[(2 * col4 + 1) * YTS + row] = pack2(-v.z, -v.w);
        }
        __syncthreads();

        const u64*  px = xsT + ty;                                    // x rows ty+16i
        const ull2* py = reinterpret_cast<const ull2*>(ysT + 2 * tx); // y cols 2tx,2tx+1

        #pragma unroll 8
        for (int dd2 = 0; dd2 < NDD2C; dd2++) {
            u64 xv[4];
            #pragma unroll
            for (int i = 0; i < 4; i++) xv[i] = px[16 * i];   // LDS.64 broadcast
            ull2 yv = *py;                                    // LDS.128 contiguous

            #pragma unroll
            for (int i = 0; i < 4; i++) {
                u64 e0 = fadd2(xv[i], yv.x);                  // x - y, col 2tx
                u64 e1 = fadd2(xv[i], yv.y);                  // col 2tx+1
                acc2[i][0] = ffma2(e0, e0, acc2[i][0]);
                acc2[i][1] = ffma2(e1, e1, acc2[i][1]);
                acc1[i][0] = fadd2(acc1[i][0], e0 & ABSM);
                acc1[i][1] = fadd2(acc1[i][1], e1 & ABSM);
            }

            px += XTS;
            py += YTS / 2;
        }
        __syncthreads();
    }

    // ---- epilogue: cos / p1 / p2 ----
    #pragma unroll
    for (int i = 0; i < 4; i++) {
        int gr = R0 + ty + 16 * i;
        float xsq = g_xsq[gr];
        float xrn = g_xrn[gr];
        #pragma unroll
        for (int j = 0; j < 2; j++) {
            int gc = C0 + 2 * tx + j;
            float s2 = f2lo(acc2[i][j]) + f2hi(acc2[i][j]);
            float s1 = f2lo(acc1[i][j]) + f2hi(acc1[i][j]);
            float p2 = sqrtf(fmaxf(s2, 0.0f));
            float dot = 0.5f * (xsq + g_ysq[gc] - s2);
            float cosv = dot * xrn * g_yrn[gc];
            size_t idx = ((size_t)gr * C_TOTAL + gc) * 3;
            out[idx + 0] = cosv;
            out[idx + 1] = s1;
            out[idx + 2] = p2;
        }
    }
}

extern "C" void kernel_launch(void* const* d_in, const int* in_sizes, int n_in,
                              void* d_out, int out_size) {
    const float* x = (const float*)d_in[0];
    const float* y = (const float*)d_in[1];
    float* out = (float*)d_out;

    // Max L1 carveout for shared memory so 4 CTAs x 25.3KB are co-resident.
    static int attr_done = 0;
    if (!attr_done) {
        cudaFuncSetAttribute(dist_kernel,
                             cudaFuncAttributePreferredSharedMemoryCarveout, 100);
        attr_done = 1;
    }

    norms_kernel<<<(2560 * 32 + 255) / 256, 256>>>(x, y);

    dim3 grid(R_TOTAL / BM, C_TOTAL / BN);   // 32 x 16 = 512 blocks, 4 CTA/SM -> 1 wave
    dist_kernel<<<grid, 256>>>(x, y, out);
}

// round 12
// speedup vs baseline: 1.5384x; 1.3117x over previous
#include <cuda_runtime.h>
#include <cstdint>

// x [4,512,128] f32, y [512,128] f32 -> out [4,512,512,3] f32 (cos, L1, L2)
#define R_TOTAL 2048
#define C_TOTAL 512
#define D_DIM   128
#define NDD2    64              // packed-pair (2 D-values) steps

#define BM 128                  // x rows per block
#define BN 64                   // y rows per block
#define XTS 129                 // xsT row stride in u64 ([dd2][row=128] + 1 pad)
#define YTS 66                  // ysT row stride in u64 ([dd2][row=64]  + 2 pad, 16B align)
#define NORM_OFF (NDD2 * XTS + NDD2 * YTS)          // u64 offset of norm area
#define SMEM_BYTES (NORM_OFF * 8 + 192 * 2 * 4)     // tiles + 192 (sq,rn) floats

typedef unsigned long long u64;
struct __align__(16) ull2 { u64 x, y; };

// ---------------- packed f32x2 helpers ----------------
__device__ __forceinline__ u64 ffma2(u64 a, u64 b, u64 c) {
    u64 d;
    asm("fma.rn.f32x2 %0, %1, %2, %3;" : "=l"(d) : "l"(a), "l"(b), "l"(c));
    return d;
}
__device__ __forceinline__ u64 fadd2(u64 a, u64 b) {
    u64 d;
    asm("add.rn.f32x2 %0, %1, %2;" : "=l"(d) : "l"(a), "l"(b));
    return d;
}
__device__ __forceinline__ float f2lo(u64 d) { return __uint_as_float((unsigned)(d & 0xFFFFFFFFu)); }
__device__ __forceinline__ float f2hi(u64 d) { return __uint_as_float((unsigned)(d >> 32)); }
__device__ __forceinline__ u64 pack2(float lo, float hi) {
    return ((u64)__float_as_uint(hi) << 32) | (u64)__float_as_uint(lo);
}

// ---------------- fused distance kernel ----------------
// 512 threads, 1 CTA/SM. tx = t&31 -> y cols {2tx, 2tx+1}; ty = t>>5 -> x rows ty+16i (i<8)
// y tile stored NEGATED: diff = x + (-y) is FADD2 (rt=2).
__global__ void __launch_bounds__(512, 1)
dist_kernel(const float* __restrict__ x, const float* __restrict__ y,
            float* __restrict__ out) {
    extern __shared__ __align__(16) u64 sm64[];
    u64* xsT = sm64;                    // [NDD2][XTS]
    u64* ysT = sm64 + NDD2 * XTS;       // [NDD2][YTS] (holds -y)
    float* nsq = reinterpret_cast<float*>(sm64 + NORM_OFF);  // [192]: 128 x + 64 y
    float* nrn = nsq + 192;

    const int R0 = blockIdx.x * BM;     // grid.x = 16
    const int C0 = blockIdx.y * BN;     // grid.y = 8
    const int t  = threadIdx.x;
    const int tx = t & 31;
    const int ty = t >> 5;

    // ---- stage x tile (128 rows x 128 cols): 8 float4 per thread
    #pragma unroll
    for (int s = 0; s < 8; s++) {
        int idx  = t + 512 * s;         // 0..4095
        int row  = idx >> 5;            // 0..127
        int col4 = idx & 31;
        float4 v = *reinterpret_cast<const float4*>(
            x + (size_t)(R0 + row) * D_DIM + col4 * 4);
        xsT[(2 * col4) * XTS + row]     = pack2(v.x, v.y);
        xsT[(2 * col4 + 1) * XTS + row] = pack2(v.z, v.w);
    }
    // ---- stage y tile NEGATED (64 rows x 128 cols): 4 float4 per thread
    #pragma unroll
    for (int s = 0; s < 4; s++) {
        int idx  = t + 512 * s;         // 0..2047
        int row  = idx >> 5;            // 0..63
        int col4 = idx & 31;
        float4 v = *reinterpret_cast<const float4*>(
            y + (size_t)(C0 + row) * D_DIM + col4 * 4);
        ysT[(2 * col4) * YTS + row]     = pack2(-v.x, -v.y);
        ysT[(2 * col4 + 1) * YTS + row] = pack2(-v.z, -v.w);
    }
    __syncthreads();

    // ---- fused norms ((-y)^2 == y^2): t<128 -> x row t; 128<=t<192 -> y col t-128
    if (t < 192) {
        const u64* base; int stride;
        if (t < 128) { base = xsT + t;         stride = XTS; }
        else         { base = ysT + (t - 128); stride = YTS; }
        u64 a = 0ULL;
        #pragma unroll 8
        for (int dd2 = 0; dd2 < NDD2; dd2++) {
            u64 v = base[dd2 * stride];
            a = ffma2(v, v, a);
        }
        float s = f2lo(a) + f2hi(a);
        nsq[t] = s;
        nrn[t] = rsqrtf(s);
    }
    __syncthreads();

    const u64 ABSM = 0x7FFFFFFF7FFFFFFFULL;   // packed abs mask

    u64 acc1[8][2];   // packed L1 sums   [x-row i][y-col j]
    u64 acc2[8][2];   // packed sum of squares
    #pragma unroll
    for (int i = 0; i < 8; i++)
        #pragma unroll
        for (int j = 0; j < 2; j++) { acc1[i][j] = 0ULL; acc2[i][j] = 0ULL; }

    const u64*  px = xsT + ty;                                    // x rows ty+16i
    const ull2* py = reinterpret_cast<const ull2*>(ysT + 2 * tx); // y cols 2tx,2tx+1

    #pragma unroll 4
    for (int dd2 = 0; dd2 < NDD2; dd2++) {
        u64 xv[8];
        #pragma unroll
        for (int i = 0; i < 8; i++) xv[i] = px[16 * i];   // LDS.64 broadcast (16 addrs)
        ull2 yv = *py;                                    // LDS.128 contiguous

        #pragma unroll
        for (int i = 0; i < 8; i++) {
            u64 e0 = fadd2(xv[i], yv.x);                  // x - y, col 2tx   (rt=2)
            u64 e1 = fadd2(xv[i], yv.y);                  // col 2tx+1
            acc2[i][0] = ffma2(e0, e0, acc2[i][0]);
            acc2[i][1] = ffma2(e1, e1, acc2[i][1]);
            acc1[i][0] = fadd2(acc1[i][0], e0 & ABSM);
            acc1[i][1] = fadd2(acc1[i][1], e1 & ABSM);
        }

        px += XTS;
        py += YTS / 2;
    }

    // ---- epilogue: cos / p1 / p2; 6 consecutive floats per row -> 3x STG.64
    #pragma unroll
    for (int i = 0; i < 8; i++) {
        int lrow = ty + 16 * i;
        int gr = R0 + lrow;
        float xsq = nsq[lrow];
        float xrn = nrn[lrow];
        float o[6];
        #pragma unroll
        for (int j = 0; j < 2; j++) {
            int lcol = 2 * tx + j;
            float s2 = f2lo(acc2[i][j]) + f2hi(acc2[i][j]);
            float s1 = f2lo(acc1[i][j]) + f2hi(acc1[i][j]);
            float p2 = sqrtf(fmaxf(s2, 0.0f));
            float dot = 0.5f * (xsq + nsq[128 + lcol] - s2);
            float cosv = dot * xrn * nrn[128 + lcol];
            o[3 * j + 0] = cosv;
            o[3 * j + 1] = s1;
            o[3 * j + 2] = p2;
        }
        // base = (gr*512 + C0 + 2tx)*3 : even index -> 8B aligned, 6 floats
        size_t base = ((size_t)gr * C_TOTAL + C0 + 2 * tx) * 3;
        float2* dst = reinterpret_cast<float2*>(out + base);
        dst[0] = make_float2(o[0], o[1]);
        dst[1] = make_float2(o[2], o[3]);
        dst[2] = make_float2(o[4], o[5]);
    }
}

extern "C" void kernel_launch(void* const* d_in, const int* in_sizes, int n_in,
                              void* d_out, int out_size) {
    const float* x = (const float*)d_in[0];
    const float* y = (const float*)d_in[1];
    float* out = (float*)d_out;

    cudaFuncSetAttribute(dist_kernel,
                         cudaFuncAttributeMaxDynamicSharedMemorySize, SMEM_BYTES);

    dim3 grid(R_TOTAL / BM, C_TOTAL / BN);   // 16 x 8 = 128 blocks, 1 CTA/SM, one wave
    dist_kernel<<<grid, 512, SMEM_BYTES>>>(x, y, out);
}